// round 2
// baseline (speedup 1.0000x reference)
#include <cuda_runtime.h>
#include <cstdint>

#define CIN    32
#define NK     64
#define HW     128
#define TILE_H 16
#define TILE_W 64
#define KO     16          // output channels per block
#define KP     (KO/2)      // packed k-pairs = 8
#define SM_W   (TILE_W+2)  // 66
#define SM_H   (TILE_H+2)  // 18
#define NTHREADS 256

typedef unsigned long long u64;

__device__ __forceinline__ u64 pk2(float lo, float hi) {
    u64 r;
    asm("mov.b64 %0, {%1, %2};" : "=l"(r) : "f"(lo), "f"(hi));
    return r;
}
__device__ __forceinline__ void fma2(u64& acc, u64 a, u64 b) {
    asm("fma.rn.f32x2 %0, %1, %2, %0;" : "+l"(acc) : "l"(a), "l"(b));
}
__device__ __forceinline__ void unpk2(float& lo, float& hi, u64 v) {
    asm("mov.b64 {%0, %1}, %2;" : "=f"(lo), "=f"(hi) : "l"(v));
}

__global__ __launch_bounds__(NTHREADS, 2)
void conv2d_k3_kernel(const float* __restrict__ x,
                      const float* __restrict__ kern,
                      const float* __restrict__ bias,
                      float* __restrict__ out)
{
    // weights pre-paired: [c][tap][kp] -> float2 (k = ko_base+2kp, ko_base+2kp+1)
    __shared__ u64   wsm[CIN * 9 * KP];        // 18 KB
    __shared__ float insm[SM_H * SM_W];        // 4752 B

    const int tx = threadIdx.x & 31;   // 0..31
    const int ty = threadIdx.x >> 5;   // 0..7

    const int wblk = blockIdx.x;               // 0..1
    const int hblk = blockIdx.y;               // 0..7
    const int z    = blockIdx.z;               // n*4 + kg
    const int n    = z >> 2;
    const int kg   = z & 3;
    const int ko_base = kg * KO;
    const int h_base  = hblk * TILE_H;
    const int w_base  = wblk * TILE_W;

    // ---- preload & repack weights for this ko-group ----
    {
        float* wf = reinterpret_cast<float*>(wsm);
        for (int i = threadIdx.x; i < CIN * 9 * KO; i += NTHREADS) {
            const int half = i & 1;
            const int kp   = (i >> 1) & 7;
            const int ct   = i >> 4;           // c*9 + tap
            const int k    = ko_base + kp * 2 + half;
            wf[i] = kern[k * (CIN * 9) + ct];
        }
    }

    // ---- accumulators init = bias ----
    u64 acc[4][KP];
    #pragma unroll
    for (int kp = 0; kp < KP; ++kp) {
        const int k0 = ko_base + 2 * kp;
        const u64 b  = pk2(bias[k0], bias[k0 + 1]);
        #pragma unroll
        for (int sp = 0; sp < 4; ++sp) acc[sp][kp] = b;
    }

    const float* xn = x + (size_t)n * CIN * HW * HW;

    for (int c = 0; c < CIN; ++c) {
        __syncthreads();   // (also covers weight-store visibility on c==0)
        // stage input tile (halo of 1) for channel c
        const float* xc = xn + c * HW * HW;
        for (int i = threadIdx.x; i < SM_H * SM_W; i += NTHREADS) {
            const int row = i / SM_W;
            const int col = i - row * SM_W;
            const int gh  = h_base + row - 1;
            const int gw  = w_base + col - 1;
            float v = 0.0f;
            if ((unsigned)gh < (unsigned)HW && (unsigned)gw < (unsigned)HW)
                v = xc[gh * HW + gw];
            insm[i] = v;
        }
        __syncthreads();

        const u64* wc = &wsm[c * 9 * KP];
        #pragma unroll
        for (int t = 0; t < 9; ++t) {
            const int r = t / 3;
            const int s = t - 3 * r;

            u64 wp[KP];
            #pragma unroll
            for (int kp = 0; kp < KP; ++kp) wp[kp] = wc[t * KP + kp];

            const float i00 = insm[(ty +     r) * SM_W + tx      + s];
            const float i01 = insm[(ty +     r) * SM_W + tx + 32 + s];
            const float i10 = insm[(ty + 8 + r) * SM_W + tx      + s];
            const float i11 = insm[(ty + 8 + r) * SM_W + tx + 32 + s];

            const u64 p00 = pk2(i00, i00);
            const u64 p01 = pk2(i01, i01);
            const u64 p10 = pk2(i10, i10);
            const u64 p11 = pk2(i11, i11);

            #pragma unroll
            for (int kp = 0; kp < KP; ++kp) {
                fma2(acc[0][kp], p00, wp[kp]);
                fma2(acc[1][kp], p01, wp[kp]);
                fma2(acc[2][kp], p10, wp[kp]);
                fma2(acc[3][kp], p11, wp[kp]);
            }
        }
    }

    // ---- store ----
    #pragma unroll
    for (int sp = 0; sp < 4; ++sp) {
        const int h = h_base + ty + (sp >> 1) * 8;
        const int w = w_base + tx + (sp & 1) * 32;
        #pragma unroll
        for (int kp = 0; kp < KP; ++kp) {
            float lo, hi;
            unpk2(lo, hi, acc[sp][kp]);
            const int k0 = ko_base + 2 * kp;
            out[(((size_t)n * NK + k0    ) * HW + h) * HW + w] = lo;
            out[(((size_t)n * NK + k0 + 1) * HW + h) * HW + w] = hi;
        }
    }
}

extern "C" void kernel_launch(void* const* d_in, const int* in_sizes, int n_in,
                              void* d_out, int out_size)
{
    const float* x    = (const float*)d_in[0];
    const float* kern = (const float*)d_in[1];
    const float* bias = (const float*)d_in[2];
    float* out = (float*)d_out;

    dim3 grid(HW / TILE_W, HW / TILE_H, 32 * (NK / KO)); // (2, 8, 128)
    dim3 block(NTHREADS, 1, 1);
    conv2d_k3_kernel<<<grid, block>>>(x, kern, bias, out);
}